// round 6
// baseline (speedup 1.0000x reference)
#include <cuda_runtime.h>
#include <cuda_bf16.h>
#include <math.h>

#define BB    32
#define T_DIM 2048
#define DIN   1024
#define DH    64
#define DC    16
#define KW    7
#define NT    2

// Emission tiling
#define TT 122          // output timesteps per CTA
#define RR 128          // h1 rows per CTA (TT + 6 halo)
#define KC 64           // K chunk per smem stage
#define NCHUNK (DIN / KC)   // 16

// All smem tiles use 32-bit-word pitch 36 (32 data words + 4 pad):
// fragment banks = 4*qr + qc + const -> conflict-free for every access pattern.
#define P36 36
#define XS0_OFF 0                          // [128][36] stage-0 x tile (bf16x2)
#define WS0_OFF (XS0_OFF + RR * P36)       // [64][36]  stage-0 W1 chunk
#define XS1_OFF (WS0_OFF + DH * P36)       // [128][36] stage-1 x tile
#define WS1_OFF (XS1_OFF + RR * P36)       // [64][36]  stage-1 W1 chunk
#define WCS_OFF (WS1_OFF + DH * P36)       // [7][16][36] conv weights
#define SMEM_WORDS (WCS_OFF + KW * DC * P36)   // 17856 words = 71424 B
#define SMEM_BYTES (SMEM_WORDS * 4)

// Scratch (allocation-free rule: __device__ globals)
__device__ __align__(16) float g_emis[BB * T_DIM * 2];   // emissions [b][t][n]

// ---------------------------------------------------------------------------
// bf16 helpers
// ---------------------------------------------------------------------------
__device__ __forceinline__ unsigned pack_bf16(float lo, float hi) {
    unsigned r;
    asm("cvt.rn.bf16x2.f32 %0, %1, %2;" : "=r"(r) : "f"(hi), "f"(lo));
    return r;
}

__device__ __forceinline__ void mma_bf16(float* d,
                                         unsigned a0, unsigned a1, unsigned a2, unsigned a3,
                                         unsigned b0, unsigned b1) {
    asm volatile("mma.sync.aligned.m16n8k16.row.col.f32.bf16.bf16.f32 "
                 "{%0,%1,%2,%3}, {%4,%5,%6,%7}, {%8,%9}, {%0,%1,%2,%3};"
                 : "+f"(d[0]), "+f"(d[1]), "+f"(d[2]), "+f"(d[3])
                 : "r"(a0), "r"(a1), "r"(a2), "r"(a3), "r"(b0), "r"(b1));
}

// ---------------------------------------------------------------------------
// Kernel 1: fused emission, bf16 tensor-core GEMM + conv.
// Double-buffered smem pipeline: one barrier per k-chunk; STS of chunk c+1
// overlaps MMAs of chunk c; LDGs for chunk c+2 issued before chunk c's MMAs.
// One CTA = one (batch, 122-t tile). 256 threads, 8 warps.
// ---------------------------------------------------------------------------
__global__ void __launch_bounds__(256, 2)
emission_kernel(const float* __restrict__ x,
                const float* __restrict__ W1,
                const float* __restrict__ b1,
                const float* __restrict__ Wc,
                const float* __restrict__ bc,
                const float* __restrict__ W2,
                const float* __restrict__ b2,
                float* __restrict__ out)
{
    extern __shared__ unsigned sw[];
    unsigned* xsb[2] = { sw + XS0_OFF, sw + XS1_OFF };
    unsigned* wsb[2] = { sw + WS0_OFF, sw + WS1_OFF };
    unsigned* wcs    = sw + WCS_OFF;

    const int tid  = threadIdx.x;
    const int lane = tid & 31;
    const int warp = tid >> 5;
    const int qr   = lane >> 2;     // 0..7
    const int qc   = lane & 3;      // 0..3
    const int b    = blockIdx.y;
    const int t0   = blockIdx.x * TT;
    const int t_base = t0 - 3;
    const float* xb = x + (size_t)b * T_DIM * DIN;

    // zero the scalar output once (crf runs in a later kernel -> ordered)
    if (blockIdx.x == 0 && blockIdx.y == 0 && tid == 0) *out = 0.f;

    // thread -> tile coords (fixed across chunks)
    const int xr = tid >> 4;            // unused placeholder
    (void)xr;

    // ---- preload conv weights: wcs[k][c][hw] = pack(Wc[c][2hw][k], Wc[c][2hw+1][k])
    for (int d = tid; d < KW * DC * (DH / 2); d += 256) {
        int hw = d & 31;
        int c  = (d >> 5) & 15;
        int k  = d >> 9;
        float lo = __ldg(Wc + ((size_t)c * DH + 2 * hw)     * KW + k);
        float hi = __ldg(Wc + ((size_t)c * DH + 2 * hw + 1) * KW + k);
        wcs[(k * DC + c) * P36 + hw] = pack_bf16(lo, hi);
    }

    float acc[8][4];
#pragma unroll
    for (int j = 0; j < 8; j++)
#pragma unroll
        for (int i = 0; i < 4; i++) acc[j][i] = 0.f;

    // per-thread prefetch registers
    float4 px[8];   // x tile: 2048 float4 / 256 thr = 8
    float4 pw[4];   // W chunk: 1024 float4 / 256 thr = 4

#define PREFETCH(k0)                                                          \
    {                                                                         \
        _Pragma("unroll")                                                     \
        for (int it = 0; it < 8; it++) {                                      \
            int idx = tid + it * 256;                                         \
            int r = idx >> 4, q = idx & 15;                                   \
            int t = t_base + r;                                               \
            px[it] = (t >= 0 && t < T_DIM)                                    \
                       ? *(const float4*)(xb + (size_t)t * DIN + (k0) + q * 4)\
                       : make_float4(0.f, 0.f, 0.f, 0.f);                     \
        }                                                                     \
        _Pragma("unroll")                                                     \
        for (int it = 0; it < 4; it++) {                                      \
            int idx = tid + it * 256;                                         \
            int h = idx >> 4, q = idx & 15;                                   \
            pw[it] = *(const float4*)(W1 + (size_t)h * DIN + (k0) + q * 4);   \
        }                                                                     \
    }

#define STORE_STAGE(s)                                                        \
    {                                                                         \
        unsigned* xs_ = xsb[s];                                               \
        unsigned* ws_ = wsb[s];                                               \
        _Pragma("unroll")                                                     \
        for (int it = 0; it < 8; it++) {                                      \
            int idx = tid + it * 256;                                         \
            int r = idx >> 4, q = idx & 15;                                   \
            float4 v = px[it];                                                \
            *(uint2*)(xs_ + r * P36 + 2 * q) =                                \
                make_uint2(pack_bf16(v.x, v.y), pack_bf16(v.z, v.w));         \
        }                                                                     \
        _Pragma("unroll")                                                     \
        for (int it = 0; it < 4; it++) {                                      \
            int idx = tid + it * 256;                                         \
            int h = idx >> 4, q = idx & 15;                                   \
            float4 v = pw[it];                                                \
            *(uint2*)(ws_ + h * P36 + 2 * q) =                                \
                make_uint2(pack_bf16(v.x, v.y), pack_bf16(v.z, v.w));         \
        }                                                                     \
    }

    // ---- prologue: chunk0 -> stage0, chunk1 in registers ----
    PREFETCH(0);
    STORE_STAGE(0);
    PREFETCH(KC);
    __syncthreads();

    const int r0 = warp * 16 + qr;
    for (int c = 0; c < NCHUNK; c++) {
        const int cur = c & 1;
        // store chunk c+1 into the other stage (its prior readers finished at
        // the barrier that ended iteration c-1)
        if (c + 1 < NCHUNK) STORE_STAGE(cur ^ 1);
        // issue chunk c+2 global loads (latency covered by MMAs + next barrier)
        if (c + 2 < NCHUNK) PREFETCH((c + 2) * KC);

        // ---- 4 k16-steps of m16n8k16 on stage `cur` ----
        const unsigned* xs_ = xsb[cur];
        const unsigned* ws_ = wsb[cur];
#pragma unroll
        for (int ks = 0; ks < KC / 16; ks++) {
            int kw = ks * 8;   // word base
            unsigned a0 = xs_[r0 * P36 + kw + qc];
            unsigned a1 = xs_[(r0 + 8) * P36 + kw + qc];
            unsigned a2 = xs_[r0 * P36 + kw + qc + 4];
            unsigned a3 = xs_[(r0 + 8) * P36 + kw + qc + 4];
#pragma unroll
            for (int j = 0; j < 8; j++) {
                unsigned b0 = ws_[(j * 8 + qr) * P36 + kw + qc];
                unsigned b1r = ws_[(j * 8 + qr) * P36 + kw + qc + 4];
                mma_bf16(acc[j], a0, a1, a2, a3, b0, b1r);
            }
        }
        __syncthreads();
    }

    // ---- GEMM epilogue: h1 = relu(acc + b1) stored to stage0 xs as bf16x2 ----
    {
        unsigned* xs_ = xsb[0];
        const int rr1 = r0 + 8;
        const int tA = t_base + r0, tB = t_base + rr1;
        const bool vA = (tA >= 0 && tA < T_DIM);
        const bool vB = (tB >= 0 && tB < T_DIM);
#pragma unroll
        for (int j = 0; j < 8; j++) {
            int c0 = j * 8 + 2 * qc, c1 = c0 + 1;
            float bv0 = __ldg(b1 + c0), bv1 = __ldg(b1 + c1);
            float hA0 = vA ? fmaxf(acc[j][0] + bv0, 0.f) : 0.f;
            float hA1 = vA ? fmaxf(acc[j][1] + bv1, 0.f) : 0.f;
            float hB0 = vB ? fmaxf(acc[j][2] + bv0, 0.f) : 0.f;
            float hB1 = vB ? fmaxf(acc[j][3] + bv1, 0.f) : 0.f;
            xs_[r0  * P36 + 4 * j + qc] = pack_bf16(hA0, hA1);
            xs_[rr1 * P36 + 4 * j + qc] = pack_bf16(hB0, hB1);
        }
    }
    __syncthreads();

    // ---- conv as 7 shifted MMAs: D[r][c] = sum_k sum_h h1[r+k][h]*wc[k][h][c] ----
    float acc2[2][4];
#pragma unroll
    for (int j = 0; j < 2; j++)
#pragma unroll
        for (int i = 0; i < 4; i++) acc2[j][i] = 0.f;

    {
        const unsigned* xs_ = xsb[0];
        const int wb2 = warp * 16;
#pragma unroll
        for (int k = 0; k < KW; k++) {
            const unsigned* wck = wcs + k * DC * P36;
            int ra = wb2 + k + qr;
            // rows >127 (feeding discarded outputs >=TT) read inside the smem
            // allocation (stage-0 ws region) -> harmless garbage.
#pragma unroll
            for (int s = 0; s < DH / 16; s++) {
                int hw = s * 8;
                unsigned a0 = xs_[ra * P36 + hw + qc];
                unsigned a1 = xs_[(ra + 8) * P36 + hw + qc];
                unsigned a2 = xs_[ra * P36 + hw + qc + 4];
                unsigned a3 = xs_[(ra + 8) * P36 + hw + qc + 4];
#pragma unroll
                for (int j = 0; j < 2; j++) {
                    unsigned b0 = wck[(j * 8 + qr) * P36 + hw + qc];
                    unsigned b1r = wck[(j * 8 + qr) * P36 + hw + qc + 4];
                    mma_bf16(acc2[j], a0, a1, a2, a3, b0, b1r);
                }
            }
        }
    }

    // ---- +bc, relu, project 16->2, reduce across qc, store emissions ----
    {
        float e0a = 0.f, e1a = 0.f, e0b = 0.f, e1b = 0.f;
#pragma unroll
        for (int j = 0; j < 2; j++) {
            int c0 = j * 8 + 2 * qc, c1 = c0 + 1;
            float bc0 = __ldg(bc + c0), bc1 = __ldg(bc + c1);
            float w00 = __ldg(W2 + c0),      w01 = __ldg(W2 + c1);
            float w10 = __ldg(W2 + DC + c0), w11 = __ldg(W2 + DC + c1);
            float hA0 = fmaxf(acc2[j][0] + bc0, 0.f), hA1 = fmaxf(acc2[j][1] + bc1, 0.f);
            float hB0 = fmaxf(acc2[j][2] + bc0, 0.f), hB1 = fmaxf(acc2[j][3] + bc1, 0.f);
            e0a = fmaf(hA0, w00, fmaf(hA1, w01, e0a));
            e1a = fmaf(hA0, w10, fmaf(hA1, w11, e1a));
            e0b = fmaf(hB0, w00, fmaf(hB1, w01, e0b));
            e1b = fmaf(hB0, w10, fmaf(hB1, w11, e1b));
        }
#pragma unroll
        for (int m = 1; m <= 2; m <<= 1) {
            e0a += __shfl_xor_sync(0xffffffffu, e0a, m);
            e1a += __shfl_xor_sync(0xffffffffu, e1a, m);
            e0b += __shfl_xor_sync(0xffffffffu, e0b, m);
            e1b += __shfl_xor_sync(0xffffffffu, e1b, m);
        }
        if (qc == 0) {
            const float bz0 = __ldg(b2 + 0), bz1 = __ldg(b2 + 1);
            int rA = warp * 16 + qr, rB = rA + 8;
            if (rA < TT && t0 + rA < T_DIM)
                *(float2*)(g_emis + ((size_t)b * T_DIM + t0 + rA) * 2) =
                    make_float2(e0a + bz0, e1a + bz1);
            if (rB < TT && t0 + rB < T_DIM)
                *(float2*)(g_emis + ((size_t)b * T_DIM + t0 + rB) * 2) =
                    make_float2(e0b + bz0, e1b + bz1);
        }
    }
#undef PREFETCH
#undef STORE_STAGE
}

// ---------------------------------------------------------------------------
// Kernel 2: CRF NLL. One CTA per batch; forward scan = ordered product of 2x2
// log-semiring matrices -> tree reduction. 512 threads x 4 steps; fast lse2.
// ---------------------------------------------------------------------------
#define CT 512

__device__ __forceinline__ float lse2(float a, float b) {
    float mx = fmaxf(a, b);
    float mn = fminf(a, b);
    // MUFU-based: abs err ~2e-7/step; random-walk over 2048 steps -> ~1e-5 abs
    return mx + __logf(1.f + __expf(mn - mx));
}

__global__ void __launch_bounds__(CT)
crf_kernel(const int* __restrict__ mask,
           const int* __restrict__ labels,
           const float* __restrict__ start_t,
           const float* __restrict__ end_t,
           const float* __restrict__ trans,
           float* __restrict__ out)
{
    __shared__ float sP[CT][4];
    __shared__ float sNum[CT];
    __shared__ int   sCnt[CT];

    const int b = blockIdx.x, tid = threadIdx.x;
    const float* em = g_emis + (size_t)b * T_DIM * 2;
    const int* mk = mask + (size_t)b * T_DIM;
    const int* lb = labels + (size_t)b * T_DIM;

    const float t00 = trans[0], t01 = trans[1], t10 = trans[2], t11 = trans[3];

    // prefetch this thread's 4-timestep slab (batched loads -> MLP)
    const int s = 1 + tid * 4;
    float2 ev[4]; int mv[4], lv[4];
#pragma unroll
    for (int i = 0; i < 4; i++) {
        int t = s + i;
        bool ok = (t < T_DIM);
        mv[i] = ok ? mk[t] : 0;
        lv[i] = ok ? lb[t] : 0;
        ev[i] = ok ? ((const float2*)em)[t] : make_float2(0.f, 0.f);
    }
    int lprev = lb[s - 1];

    float P00 = 0.f, P01 = -1e30f, P10 = -1e30f, P11 = 0.f;  // identity
    float num = 0.f;
    int cnt = 0;

#pragma unroll
    for (int i = 0; i < 4; i++) {
        if (mv[i] != 0) {
            cnt++;
            int lc = lv[i];
            float tv = lprev ? (lc ? t11 : t10) : (lc ? t01 : t00);
            num += tv + (lc ? ev[i].y : ev[i].x);
            float M00 = t00 + ev[i].x, M01 = t01 + ev[i].y;
            float M10 = t10 + ev[i].x, M11 = t11 + ev[i].y;
            float c00 = lse2(P00 + M00, P01 + M10);
            float c01 = lse2(P00 + M01, P01 + M11);
            float c10 = lse2(P10 + M00, P11 + M10);
            float c11 = lse2(P10 + M01, P11 + M11);
            P00 = c00; P01 = c01; P10 = c10; P11 = c11;
        }
        lprev = lv[i];
    }

    sP[tid][0] = P00; sP[tid][1] = P01; sP[tid][2] = P10; sP[tid][3] = P11;
    sNum[tid] = num; sCnt[tid] = cnt;
    __syncthreads();

    // ordered tree combine: left ⊗ right
    for (int off = CT / 2; off > 0; off >>= 1) {
        if (tid < off) {
            float A00 = sP[tid][0], A01 = sP[tid][1], A10 = sP[tid][2], A11 = sP[tid][3];
            float B00 = sP[tid + off][0], B01 = sP[tid + off][1];
            float B10 = sP[tid + off][2], B11 = sP[tid + off][3];
            sP[tid][0] = lse2(A00 + B00, A01 + B10);
            sP[tid][1] = lse2(A00 + B01, A01 + B11);
            sP[tid][2] = lse2(A10 + B00, A11 + B10);
            sP[tid][3] = lse2(A10 + B01, A11 + B11);
            sNum[tid] += sNum[tid + off];
            sCnt[tid] += sCnt[tid + off];
        }
        __syncthreads();
    }

    if (tid == 0) {
        float a0 = start_t[0] + em[0];
        float a1 = start_t[1] + em[1];
        float f0 = lse2(a0 + sP[0][0], a1 + sP[0][2]);
        float f1 = lse2(a0 + sP[0][1], a1 + sP[0][3]);
        float logZ = lse2(f0 + end_t[0], f1 + end_t[1]);

        int total = sCnt[0] + (mk[0] != 0 ? 1 : 0);
        int last = max(total - 1, 0);
        int l0 = lb[0];
        float numT = sNum[0] + start_t[l0] + (l0 ? em[1] : em[0]) + end_t[lb[last]];
        atomicAdd(out, logZ - numT);   // loss = sum_b (logZ - num)
    }
}

// ---------------------------------------------------------------------------
extern "C" void kernel_launch(void* const* d_in, const int* in_sizes, int n_in,
                              void* d_out, int out_size) {
    const float* x      = (const float*)d_in[0];
    const int*   mask   = (const int*)d_in[1];    // bool -> int32 per harness dtypes
    const int*   labels = (const int*)d_in[2];
    const float* W1     = (const float*)d_in[3];
    const float* b1     = (const float*)d_in[4];
    const float* Wc     = (const float*)d_in[5];
    const float* bc     = (const float*)d_in[6];
    const float* W2     = (const float*)d_in[7];
    const float* b2     = (const float*)d_in[8];
    const float* st     = (const float*)d_in[9];
    const float* et     = (const float*)d_in[10];
    const float* tr     = (const float*)d_in[11];
    float* out = (float*)d_out;

    (void)in_sizes; (void)n_in; (void)out_size;

    cudaFuncSetAttribute(emission_kernel,
                         cudaFuncAttributeMaxDynamicSharedMemorySize, SMEM_BYTES);

    dim3 egrid((T_DIM + TT - 1) / TT, BB);   // 17 x 32
    emission_kernel<<<egrid, 256, SMEM_BYTES>>>(x, W1, b1, Wc, bc, W2, b2, out);

    crf_kernel<<<BB, CT>>>(mask, labels, st, et, tr, out);
}

// round 7
// speedup vs baseline: 1.2170x; 1.2170x over previous
#include <cuda_runtime.h>
#include <cuda_bf16.h>
#include <math.h>

#define BB    32
#define T_DIM 2048
#define DIN   1024
#define DH    64
#define DC    16
#define KW    7
#define NT    2

// Emission tiling
#define TT 122          // output timesteps per CTA
#define RR 128          // h1 rows per CTA (TT + 6 halo)
#define KC 64           // K chunk per smem stage
#define NCHUNK (DIN / KC)   // 16

// All smem tiles use 32-bit-word pitch 36 (32 data words + 4 pad):
// fragment banks = 4*qr + qc + const -> conflict-free for every access pattern.
#define P36 36
#define XS0_OFF 0                          // [128][36] stage-0 x tile (bf16x2)
#define WS0_OFF (XS0_OFF + RR * P36)       // [64][36]  stage-0 W1 chunk
#define XS1_OFF (WS0_OFF + DH * P36)       // [128][36] stage-1 x tile
#define WS1_OFF (XS1_OFF + RR * P36)       // [64][36]  stage-1 W1 chunk
#define WCS_OFF (WS1_OFF + DH * P36)       // [7][16][36] conv weights
#define SMEM_WORDS (WCS_OFF + KW * DC * P36)   // 17856 words = 71424 B
#define SMEM_BYTES (SMEM_WORDS * 4)

// Scratch (allocation-free rule: __device__ globals)
__device__ __align__(16) float g_emis[BB * T_DIM * 2];   // emissions [b][t][n]

// ---------------------------------------------------------------------------
// bf16 helpers
// ---------------------------------------------------------------------------
__device__ __forceinline__ unsigned pack_bf16(float lo, float hi) {
    unsigned r;
    asm("cvt.rn.bf16x2.f32 %0, %1, %2;" : "=r"(r) : "f"(hi), "f"(lo));
    return r;
}

__device__ __forceinline__ void mma_bf16(float* d,
                                         unsigned a0, unsigned a1, unsigned a2, unsigned a3,
                                         unsigned b0, unsigned b1) {
    asm volatile("mma.sync.aligned.m16n8k16.row.col.f32.bf16.bf16.f32 "
                 "{%0,%1,%2,%3}, {%4,%5,%6,%7}, {%8,%9}, {%0,%1,%2,%3};"
                 : "+f"(d[0]), "+f"(d[1]), "+f"(d[2]), "+f"(d[3])
                 : "r"(a0), "r"(a1), "r"(a2), "r"(a3), "r"(b0), "r"(b1));
}

// ---------------------------------------------------------------------------
// Kernel 1: fused emission, bf16 tensor-core GEMM + conv.
// Double-buffered smem pipeline with STATIC stage pointers (chunk loop
// unrolled by 2). One barrier per k-chunk; STS of chunk c+1 overlaps MMAs of
// chunk c; LDGs for chunk c+2 issued before chunk c's MMAs.
// One CTA = one (batch, 122-t tile). 256 threads, 8 warps.
// ---------------------------------------------------------------------------
__global__ void __launch_bounds__(256, 2)
emission_kernel(const float* __restrict__ x,
                const float* __restrict__ W1,
                const float* __restrict__ b1,
                const float* __restrict__ Wc,
                const float* __restrict__ bc,
                const float* __restrict__ W2,
                const float* __restrict__ b2,
                float* __restrict__ out)
{
    extern __shared__ unsigned sw[];
    unsigned* const xs0 = sw + XS0_OFF;
    unsigned* const ws0 = sw + WS0_OFF;
    unsigned* const xs1 = sw + XS1_OFF;
    unsigned* const ws1 = sw + WS1_OFF;
    unsigned* const wcs = sw + WCS_OFF;

    const int tid  = threadIdx.x;
    const int lane = tid & 31;
    const int warp = tid >> 5;
    const int qr   = lane >> 2;     // 0..7
    const int qc   = lane & 3;      // 0..3
    const int b    = blockIdx.y;
    const int t0   = blockIdx.x * TT;
    const int t_base = t0 - 3;
    const float* xb = x + (size_t)b * T_DIM * DIN;

    // zero the scalar output once (crf runs in a later kernel -> ordered)
    if (blockIdx.x == 0 && blockIdx.y == 0 && tid == 0) *out = 0.f;

    // ---- preload conv weights: wcs[k][c][hw] = pack(Wc[c][2hw][k], Wc[c][2hw+1][k])
    for (int d = tid; d < KW * DC * (DH / 2); d += 256) {
        int hw = d & 31;
        int c  = (d >> 5) & 15;
        int k  = d >> 9;
        float lo = __ldg(Wc + ((size_t)c * DH + 2 * hw)     * KW + k);
        float hi = __ldg(Wc + ((size_t)c * DH + 2 * hw + 1) * KW + k);
        wcs[(k * DC + c) * P36 + hw] = pack_bf16(lo, hi);
    }

    float acc[8][4];
#pragma unroll
    for (int j = 0; j < 8; j++)
#pragma unroll
        for (int i = 0; i < 4; i++) acc[j][i] = 0.f;

    // per-thread prefetch registers
    float4 px[8];   // x tile: 2048 float4 / 256 thr = 8
    float4 pw[4];   // W chunk: 1024 float4 / 256 thr = 4

#define PREFETCH(k0)                                                          \
    {                                                                         \
        _Pragma("unroll")                                                     \
        for (int it = 0; it < 8; it++) {                                      \
            int idx = tid + it * 256;                                         \
            int r = idx >> 4, q = idx & 15;                                   \
            int t = t_base + r;                                               \
            px[it] = (t >= 0 && t < T_DIM)                                    \
                       ? *(const float4*)(xb + (size_t)t * DIN + (k0) + q * 4)\
                       : make_float4(0.f, 0.f, 0.f, 0.f);                     \
        }                                                                     \
        _Pragma("unroll")                                                     \
        for (int it = 0; it < 4; it++) {                                      \
            int idx = tid + it * 256;                                         \
            int h = idx >> 4, q = idx & 15;                                   \
            pw[it] = *(const float4*)(W1 + (size_t)h * DIN + (k0) + q * 4);   \
        }                                                                     \
    }

#define STORE_STAGE(XS, WS)                                                   \
    {                                                                         \
        _Pragma("unroll")                                                     \
        for (int it = 0; it < 8; it++) {                                      \
            int idx = tid + it * 256;                                         \
            int r = idx >> 4, q = idx & 15;                                   \
            float4 v = px[it];                                                \
            *(uint2*)((XS) + r * P36 + 2 * q) =                               \
                make_uint2(pack_bf16(v.x, v.y), pack_bf16(v.z, v.w));         \
        }                                                                     \
        _Pragma("unroll")                                                     \
        for (int it = 0; it < 4; it++) {                                      \
            int idx = tid + it * 256;                                         \
            int h = idx >> 4, q = idx & 15;                                   \
            float4 v = pw[it];                                                \
            *(uint2*)((WS) + h * P36 + 2 * q) =                               \
                make_uint2(pack_bf16(v.x, v.y), pack_bf16(v.z, v.w));         \
        }                                                                     \
    }

#define MMA_CHUNK(XS, WS)                                                     \
    {                                                                         \
        _Pragma("unroll")                                                     \
        for (int ks = 0; ks < KC / 16; ks++) {                                \
            int kw = ks * 8;                                                  \
            unsigned a0 = (XS)[r0 * P36 + kw + qc];                           \
            unsigned a1 = (XS)[(r0 + 8) * P36 + kw + qc];                     \
            unsigned a2 = (XS)[r0 * P36 + kw + qc + 4];                       \
            unsigned a3 = (XS)[(r0 + 8) * P36 + kw + qc + 4];                 \
            _Pragma("unroll")                                                 \
            for (int j = 0; j < 8; j++) {                                     \
                unsigned b0 = (WS)[(j * 8 + qr) * P36 + kw + qc];             \
                unsigned b1r = (WS)[(j * 8 + qr) * P36 + kw + qc + 4];        \
                mma_bf16(acc[j], a0, a1, a2, a3, b0, b1r);                    \
            }                                                                 \
        }                                                                     \
    }

    // ---- prologue: chunk0 -> stage0, chunk1 in registers ----
    PREFETCH(0);
    STORE_STAGE(xs0, ws0);
    PREFETCH(KC);
    __syncthreads();

    const int r0 = warp * 16 + qr;
#pragma unroll 1
    for (int c = 0; c < NCHUNK; c += 2) {
        // even chunk c: consume stage0
        if (c + 1 < NCHUNK) STORE_STAGE(xs1, ws1);         // chunk c+1 -> stage1
        if (c + 2 < NCHUNK) PREFETCH((c + 2) * KC);        // chunk c+2 -> regs
        MMA_CHUNK(xs0, ws0);
        __syncthreads();

        // odd chunk c+1: consume stage1
        if (c + 2 < NCHUNK) STORE_STAGE(xs0, ws0);         // chunk c+2 -> stage0
        if (c + 3 < NCHUNK) PREFETCH((c + 3) * KC);        // chunk c+3 -> regs
        MMA_CHUNK(xs1, ws1);
        __syncthreads();
    }

    // ---- GEMM epilogue: h1 = relu(acc + b1) stored to stage0 xs as bf16x2 ----
    {
        const int rr1 = r0 + 8;
        const int tA = t_base + r0, tB = t_base + rr1;
        const bool vA = (tA >= 0 && tA < T_DIM);
        const bool vB = (tB >= 0 && tB < T_DIM);
#pragma unroll
        for (int j = 0; j < 8; j++) {
            int c0 = j * 8 + 2 * qc, c1 = c0 + 1;
            float bv0 = __ldg(b1 + c0), bv1 = __ldg(b1 + c1);
            float hA0 = vA ? fmaxf(acc[j][0] + bv0, 0.f) : 0.f;
            float hA1 = vA ? fmaxf(acc[j][1] + bv1, 0.f) : 0.f;
            float hB0 = vB ? fmaxf(acc[j][2] + bv0, 0.f) : 0.f;
            float hB1 = vB ? fmaxf(acc[j][3] + bv1, 0.f) : 0.f;
            xs0[r0  * P36 + 4 * j + qc] = pack_bf16(hA0, hA1);
            xs0[rr1 * P36 + 4 * j + qc] = pack_bf16(hB0, hB1);
        }
    }
    __syncthreads();

    // ---- conv as 7 shifted MMAs: D[r][c] = sum_k sum_h h1[r+k][h]*wc[k][h][c] ----
    float acc2[2][4];
#pragma unroll
    for (int j = 0; j < 2; j++)
#pragma unroll
        for (int i = 0; i < 4; i++) acc2[j][i] = 0.f;

    {
        const int wb2 = warp * 16;
#pragma unroll
        for (int k = 0; k < KW; k++) {
            const unsigned* wck = wcs + k * DC * P36;
            int ra = wb2 + k + qr;
            // rows >127 (feeding discarded outputs >=TT) read inside the smem
            // allocation (stage-0 ws region) -> harmless garbage.
#pragma unroll
            for (int s = 0; s < DH / 16; s++) {
                int hw = s * 8;
                unsigned a0 = xs0[ra * P36 + hw + qc];
                unsigned a1 = xs0[(ra + 8) * P36 + hw + qc];
                unsigned a2 = xs0[ra * P36 + hw + qc + 4];
                unsigned a3 = xs0[(ra + 8) * P36 + hw + qc + 4];
#pragma unroll
                for (int j = 0; j < 2; j++) {
                    unsigned b0 = wck[(j * 8 + qr) * P36 + hw + qc];
                    unsigned b1r = wck[(j * 8 + qr) * P36 + hw + qc + 4];
                    mma_bf16(acc2[j], a0, a1, a2, a3, b0, b1r);
                }
            }
        }
    }

    // ---- +bc, relu, project 16->2, reduce across qc, store emissions ----
    {
        float e0a = 0.f, e1a = 0.f, e0b = 0.f, e1b = 0.f;
#pragma unroll
        for (int j = 0; j < 2; j++) {
            int c0 = j * 8 + 2 * qc, c1 = c0 + 1;
            float bc0 = __ldg(bc + c0), bc1 = __ldg(bc + c1);
            float w00 = __ldg(W2 + c0),      w01 = __ldg(W2 + c1);
            float w10 = __ldg(W2 + DC + c0), w11 = __ldg(W2 + DC + c1);
            float hA0 = fmaxf(acc2[j][0] + bc0, 0.f), hA1 = fmaxf(acc2[j][1] + bc1, 0.f);
            float hB0 = fmaxf(acc2[j][2] + bc0, 0.f), hB1 = fmaxf(acc2[j][3] + bc1, 0.f);
            e0a = fmaf(hA0, w00, fmaf(hA1, w01, e0a));
            e1a = fmaf(hA0, w10, fmaf(hA1, w11, e1a));
            e0b = fmaf(hB0, w00, fmaf(hB1, w01, e0b));
            e1b = fmaf(hB0, w10, fmaf(hB1, w11, e1b));
        }
#pragma unroll
        for (int m = 1; m <= 2; m <<= 1) {
            e0a += __shfl_xor_sync(0xffffffffu, e0a, m);
            e1a += __shfl_xor_sync(0xffffffffu, e1a, m);
            e0b += __shfl_xor_sync(0xffffffffu, e0b, m);
            e1b += __shfl_xor_sync(0xffffffffu, e1b, m);
        }
        if (qc == 0) {
            const float bz0 = __ldg(b2 + 0), bz1 = __ldg(b2 + 1);
            int rA = warp * 16 + qr, rB = rA + 8;
            if (rA < TT && t0 + rA < T_DIM)
                *(float2*)(g_emis + ((size_t)b * T_DIM + t0 + rA) * 2) =
                    make_float2(e0a + bz0, e1a + bz1);
            if (rB < TT && t0 + rB < T_DIM)
                *(float2*)(g_emis + ((size_t)b * T_DIM + t0 + rB) * 2) =
                    make_float2(e0b + bz0, e1b + bz1);
        }
    }
#undef PREFETCH
#undef STORE_STAGE
#undef MMA_CHUNK
}

// ---------------------------------------------------------------------------
// Kernel 2: CRF NLL. One CTA per batch; forward scan = ordered product of 2x2
// log-semiring matrices -> tree reduction. 512 threads x 4 steps; fast lse2.
// ---------------------------------------------------------------------------
#define CT 512

__device__ __forceinline__ float lse2(float a, float b) {
    float mx = fmaxf(a, b);
    float mn = fminf(a, b);
    // MUFU-based: abs err ~2e-7/step; random-walk over 2048 steps -> ~1e-5 abs
    return mx + __logf(1.f + __expf(mn - mx));
}

__global__ void __launch_bounds__(CT)
crf_kernel(const int* __restrict__ mask,
           const int* __restrict__ labels,
           const float* __restrict__ start_t,
           const float* __restrict__ end_t,
           const float* __restrict__ trans,
           float* __restrict__ out)
{
    __shared__ float sP[CT][4];
    __shared__ float sNum[CT];
    __shared__ int   sCnt[CT];

    const int b = blockIdx.x, tid = threadIdx.x;
    const float* em = g_emis + (size_t)b * T_DIM * 2;
    const int* mk = mask + (size_t)b * T_DIM;
    const int* lb = labels + (size_t)b * T_DIM;

    const float t00 = trans[0], t01 = trans[1], t10 = trans[2], t11 = trans[3];

    // prefetch this thread's 4-timestep slab (batched loads -> MLP)
    const int s = 1 + tid * 4;
    float2 ev[4]; int mv[4], lv[4];
#pragma unroll
    for (int i = 0; i < 4; i++) {
        int t = s + i;
        bool ok = (t < T_DIM);
        mv[i] = ok ? mk[t] : 0;
        lv[i] = ok ? lb[t] : 0;
        ev[i] = ok ? ((const float2*)em)[t] : make_float2(0.f, 0.f);
    }
    int lprev = lb[s - 1];

    float P00 = 0.f, P01 = -1e30f, P10 = -1e30f, P11 = 0.f;  // identity
    float num = 0.f;
    int cnt = 0;

#pragma unroll
    for (int i = 0; i < 4; i++) {
        if (mv[i] != 0) {
            cnt++;
            int lc = lv[i];
            float tv = lprev ? (lc ? t11 : t10) : (lc ? t01 : t00);
            num += tv + (lc ? ev[i].y : ev[i].x);
            float M00 = t00 + ev[i].x, M01 = t01 + ev[i].y;
            float M10 = t10 + ev[i].x, M11 = t11 + ev[i].y;
            float c00 = lse2(P00 + M00, P01 + M10);
            float c01 = lse2(P00 + M01, P01 + M11);
            float c10 = lse2(P10 + M00, P11 + M10);
            float c11 = lse2(P10 + M01, P11 + M11);
            P00 = c00; P01 = c01; P10 = c10; P11 = c11;
        }
        lprev = lv[i];
    }

    sP[tid][0] = P00; sP[tid][1] = P01; sP[tid][2] = P10; sP[tid][3] = P11;
    sNum[tid] = num; sCnt[tid] = cnt;
    __syncthreads();

    // ordered tree combine: left ⊗ right
    for (int off = CT / 2; off > 0; off >>= 1) {
        if (tid < off) {
            float A00 = sP[tid][0], A01 = sP[tid][1], A10 = sP[tid][2], A11 = sP[tid][3];
            float B00 = sP[tid + off][0], B01 = sP[tid + off][1];
            float B10 = sP[tid + off][2], B11 = sP[tid + off][3];
            sP[tid][0] = lse2(A00 + B00, A01 + B10);
            sP[tid][1] = lse2(A00 + B01, A01 + B11);
            sP[tid][2] = lse2(A10 + B00, A11 + B10);
            sP[tid][3] = lse2(A10 + B01, A11 + B11);
            sNum[tid] += sNum[tid + off];
            sCnt[tid] += sCnt[tid + off];
        }
        __syncthreads();
    }

    if (tid == 0) {
        float a0 = start_t[0] + em[0];
        float a1 = start_t[1] + em[1];
        float f0 = lse2(a0 + sP[0][0], a1 + sP[0][2]);
        float f1 = lse2(a0 + sP[0][1], a1 + sP[0][3]);
        float logZ = lse2(f0 + end_t[0], f1 + end_t[1]);

        int total = sCnt[0] + (mk[0] != 0 ? 1 : 0);
        int last = max(total - 1, 0);
        int l0 = lb[0];
        float numT = sNum[0] + start_t[l0] + (l0 ? em[1] : em[0]) + end_t[lb[last]];
        atomicAdd(out, logZ - numT);   // loss = sum_b (logZ - num)
    }
}

// ---------------------------------------------------------------------------
extern "C" void kernel_launch(void* const* d_in, const int* in_sizes, int n_in,
                              void* d_out, int out_size) {
    const float* x      = (const float*)d_in[0];
    const int*   mask   = (const int*)d_in[1];    // bool -> int32 per harness dtypes
    const int*   labels = (const int*)d_in[2];
    const float* W1     = (const float*)d_in[3];
    const float* b1     = (const float*)d_in[4];
    const float* Wc     = (const float*)d_in[5];
    const float* bc     = (const float*)d_in[6];
    const float* W2     = (const float*)d_in[7];
    const float* b2     = (const float*)d_in[8];
    const float* st     = (const float*)d_in[9];
    const float* et     = (const float*)d_in[10];
    const float* tr     = (const float*)d_in[11];
    float* out = (float*)d_out;

    (void)in_sizes; (void)n_in; (void)out_size;

    cudaFuncSetAttribute(emission_kernel,
                         cudaFuncAttributeMaxDynamicSharedMemorySize, SMEM_BYTES);

    dim3 egrid((T_DIM + TT - 1) / TT, BB);   // 17 x 32
    emission_kernel<<<egrid, 256, SMEM_BYTES>>>(x, W1, b1, Wc, bc, W2, b2, out);

    crf_kernel<<<BB, CT>>>(mask, labels, st, et, tr, out);
}